// round 1
// baseline (speedup 1.0000x reference)
#include <cuda_runtime.h>
#include <math.h>

#define BH 512
#define BW 512
#define BB 8
#define NBUK 16     // B*CLS
#define MAXT 160
#define TILE 32

// ---- device scratch (no allocations allowed) ----
__device__ float g_c [NBUK][MAXT];
__device__ float g_s [NBUK][MAXT];
__device__ float g_x3[NBUK][MAXT];
__device__ float g_x4[NBUK][MAXT];
__device__ float g_y3[NBUK][MAXT];
__device__ float g_y4[NBUK][MAXT];
__device__ int    g_cnt[NBUK];
__device__ double g_acc[8];  // [cls*4 + {sumNo,cntNo,sumObj,cntObj}]

// ------------------------------------------------------------------
// Kernel 1: preprocess targets into (batch,class) buckets, zero accums
// ------------------------------------------------------------------
__global__ void prep_kernel(const float* __restrict__ tgt, int nT) {
    __shared__ int scnt[NBUK];
    int tid = threadIdx.x;
    if (tid < NBUK) scnt[tid] = 0;
    if (tid < 8) g_acc[tid] = 0.0;
    __syncthreads();
    if (tid < nT) {
        const float* t = tgt + tid * 7;
        int bid = (int)t[0];
        int cid = (int)t[1];
        float cx = t[2] * 0.125f;   // /SCALE, exact pow2
        float cy = t[3] * 0.125f;
        float w  = t[4] * 0.125f;
        float h  = t[5] * 0.125f;
        float ang = t[6];
        float c = cosf(ang), s = sinf(ang);
        float x =  cx * c + cy * s;
        float y = -cx * s + cy * c;
        int bk = bid * 2 + cid;
        int slot = atomicAdd(&scnt[bk], 1);
        if (slot < MAXT) {
            g_c [bk][slot] = c;
            g_s [bk][slot] = s;
            g_x3[bk][slot] = x - h * 0.5f;
            g_x4[bk][slot] = x + h * 0.5f;
            g_y3[bk][slot] = y - w * 0.5f;
            g_y4[bk][slot] = y + w * 0.5f;
        }
    }
    __syncthreads();
    if (tid < NBUK) g_cnt[tid] = min(scnt[tid], MAXT);
}

// ------------------------------------------------------------------
// Kernel 2: per-pixel sigmoid/heatmap + masked log-loss accumulation.
// One block = 32x32 tile of one batch image. Tile-level AABB culling
// builds a tiny active-target list in smem (avg < 1 target/tile).
// ------------------------------------------------------------------
__global__ __launch_bounds__(256)
void main_kernel(const float* __restrict__ pred, float* __restrict__ out) {
    __shared__ float sc[2][6][MAXT];   // [cls][{c,s,x3,x4,y3,y4}][i]
    __shared__ int   nAct[2];
    __shared__ float sred[8][8];

    const int tid = threadIdx.x;
    const int b   = blockIdx.z;
    const int tx  = blockIdx.x * TILE;
    const int ty  = blockIdx.y * TILE;

    if (tid < 2) nAct[tid] = 0;
    __syncthreads();

    // -- tile culling: rotated-coords interval vs (outer) box interval --
    const float gxlo = tx + 0.5f, gxhi = tx + TILE - 0.5f;
    const float gylo = ty + 0.5f, gyhi = ty + TILE - 0.5f;
    for (int cls = 0; cls < 2; cls++) {
        int bk  = b * 2 + cls;
        int cnt = g_cnt[bk];
        for (int i = tid; i < cnt; i += 256) {
            float c  = g_c[bk][i],  s  = g_s[bk][i];
            float X3 = g_x3[bk][i], X4 = g_x4[bk][i];
            float Y3 = g_y3[bk][i], Y4 = g_y4[bk][i];
            float vxmin = fminf(c * gxlo, c * gxhi) + fminf(s * gylo, s * gyhi);
            float vxmax = fmaxf(c * gxlo, c * gxhi) + fmaxf(s * gylo, s * gyhi);
            float vymin = fminf(-s * gxlo, -s * gxhi) + fminf(c * gylo, c * gyhi);
            float vymax = fmaxf(-s * gxlo, -s * gxhi) + fmaxf(c * gylo, c * gyhi);
            if (vxmax >= X3 - 0.5f && vxmin <= X4 + 0.5f &&
                vymax >= Y3 - 0.5f && vymin <= Y4 + 0.5f) {
                int p = atomicAdd(&nAct[cls], 1);
                sc[cls][0][p] = c;  sc[cls][1][p] = s;
                sc[cls][2][p] = X3; sc[cls][3][p] = X4;
                sc[cls][4][p] = Y3; sc[cls][5][p] = Y4;
            }
        }
    }
    __syncthreads();

    // -- pixel group: 4 consecutive pixels along w per thread --
    const int row = tid >> 3;
    const int col = (tid & 7) << 2;
    const int h = ty + row;
    const int w = tx + col;
    const float* basep = pred + ((size_t)b * 2) * (BH * BW) + (size_t)h * BW + w;
    float4 p0 = *(const float4*)basep;
    float4 p1 = *(const float4*)(basep + BH * BW);
    float x0[4] = {p0.x, p0.y, p0.z, p0.w};
    float x1[4] = {p1.x, p1.y, p1.z, p1.w};
    const float gy  = h + 0.5f;
    const float gx0 = w + 0.5f;

    bool objF[2][4], outF[2][4];
    #pragma unroll
    for (int c2 = 0; c2 < 2; c2++)
        #pragma unroll
        for (int k = 0; k < 4; k++) { objF[c2][k] = false; outF[c2][k] = false; }

    #pragma unroll
    for (int cls = 0; cls < 2; cls++) {
        int n = nAct[cls];
        for (int j = 0; j < n; j++) {
            float c  = sc[cls][0][j], s  = sc[cls][1][j];
            float X3 = sc[cls][2][j], X4 = sc[cls][3][j];
            float Y3 = sc[cls][4][j], Y4 = sc[cls][5][j];
            float sgy = s * gy, cgy = c * gy;
            #pragma unroll
            for (int k = 0; k < 4; k++) {
                float gx = gx0 + (float)k;
                float vx = fmaf(c, gx, sgy);
                float vy = fmaf(-s, gx, cgy);
                bool in_ = (vx >= X3) & (vx <= X4) & (vy >= Y3) & (vy <= Y4);
                bool ot_ = (vx >= X3 - 0.5f) & (vx <= X4 + 0.5f) &
                           (vy >= Y3 - 0.5f) & (vy <= Y4 + 0.5f);
                objF[cls][k] |= in_;
                outF[cls][k] |= ot_;
            }
        }
    }

    // -- transcendental core --
    // t = e^x;  softplus(x) = log(1+t) = -log(1-sigmoid(x))
    // -log(sigmoid(x)) = log(1+t) - x
    // max(sig(x0),sig(x1)) = tm/(1+tm), tm = max(t0,t1)
    float accNo[2]  = {0.f, 0.f}, cntNo[2]  = {0.f, 0.f};
    float accOb[2]  = {0.f, 0.f}, cntOb[2]  = {0.f, 0.f};
    float hm[4];
    #pragma unroll
    for (int k = 0; k < 4; k++) {
        float t0 = __expf(x0[k]);
        float t1 = __expf(x1[k]);
        float L0 = __logf(1.0f + t0);
        float L1 = __logf(1.0f + t1);
        float tm = fmaxf(t0, t1);
        hm[k] = __fdividef(tm, 1.0f + tm);
        if (!outF[0][k]) { accNo[0] += L0;          cntNo[0] += 1.0f; }
        if ( objF[0][k]) { accOb[0] += L0 - x0[k];  cntOb[0] += 1.0f; }
        if (!outF[1][k]) { accNo[1] += L1;          cntNo[1] += 1.0f; }
        if ( objF[1][k]) { accOb[1] += L1 - x1[k];  cntOb[1] += 1.0f; }
    }
    float* hout = out + 1 + ((size_t)b * BH + h) * BW + w;
    hout[0] = hm[0]; hout[1] = hm[1]; hout[2] = hm[2]; hout[3] = hm[3];

    // -- block reduction, then double atomics --
    float vals[8] = {accNo[0], cntNo[0], accOb[0], cntOb[0],
                     accNo[1], cntNo[1], accOb[1], cntOb[1]};
    #pragma unroll
    for (int j = 0; j < 8; j++) {
        float v = vals[j];
        #pragma unroll
        for (int off = 16; off; off >>= 1)
            v += __shfl_down_sync(0xffffffffu, v, off);
        if ((tid & 31) == 0) sred[tid >> 5][j] = v;
    }
    __syncthreads();
    if (tid < 8) {
        float ssum = 0.f;
        #pragma unroll
        for (int wv = 0; wv < 8; wv++) ssum += sred[wv][tid];
        atomicAdd(&g_acc[tid], (double)ssum);
    }
}

// ------------------------------------------------------------------
// Kernel 3: final scalar loss
// ------------------------------------------------------------------
__global__ void final_kernel(float* __restrict__ out) {
    double loss = 0.0;
    #pragma unroll
    for (int cls = 0; cls < 2; cls++) {
        double sNo = g_acc[cls * 4 + 0];
        double cNo = g_acc[cls * 4 + 1];
        double sOb = g_acc[cls * 4 + 2];
        double cOb = g_acc[cls * 4 + 3];
        if (cOb > 0.0)
            loss += sOb / fmax(cOb, 1.0) + sNo / fmax(cNo, 1.0);
    }
    out[0] = (float)loss;
}

// ------------------------------------------------------------------
extern "C" void kernel_launch(void* const* d_in, const int* in_sizes, int n_in,
                              void* d_out, int out_size) {
    const float* pred = (const float*)d_in[0];
    const float* tgt  = (const float*)d_in[1];
    int nT = in_sizes[1] / 7;
    float* out = (float*)d_out;

    prep_kernel<<<1, 256>>>(tgt, nT);
    dim3 grid(BW / TILE, BH / TILE, BB);
    main_kernel<<<grid, 256>>>(pred, out);
    final_kernel<<<1, 1>>>(out);
}